// round 6
// baseline (speedup 1.0000x reference)
#include <cuda_runtime.h>

#define NN 50000
#define NE 800000
#define IND 128
#define HD 64
#define OD 64
#define NG 512

static const int SCAN_BLK = (NN + 1023) / 1024;  // 49

// ---------------- scratch (__device__ globals: no allocs allowed) ----------
__device__ int   g_is64;
__device__ int   g_degcnt[NN];
__device__ int   g_cursor[NN];
__device__ int   g_offsets[NN + 1];
__device__ int   g_blocksums[64];
__device__ int   g_blockbase[64];
__device__ float g_dinv[NN];
__device__ int   g_srcs[NE];
__device__ float g_norms[NE];
__device__ float g_t1[NN * HD];
__device__ float g_agg1[NN * HD];
__device__ float g_t2[NN * OD];
__device__ float g_agg2[NN * OD];

// ---------------- index loading (int64 vs int32 runtime detect) ------------
__device__ __forceinline__ long long ld_idx(const void* p, long long i) {
    if (g_is64) return ((const long long*)p)[i];
    return (long long)((const int*)p)[i];
}

__global__ void detect_kernel(const void* __restrict__ ei) {
    if (threadIdx.x == 0) {
        const long long* p = (const long long*)ei;
        int ok = 1;
        for (int j = 0; j < 64; j++) {
            long long v = p[j];
            if (v < 0 || v >= NN) { ok = 0; break; }
        }
        g_is64 = ok;  // int32 data read as int64 fails the range check w.h.p.
    }
}

// ---------------- CSR build ------------------------------------------------
__global__ void zero_kernel() {
    int i = blockIdx.x * blockDim.x + threadIdx.x;
    if (i < NN) { g_degcnt[i] = 0; g_cursor[i] = 0; }
}

__global__ void count_kernel(const void* __restrict__ ei) {
    int e = blockIdx.x * blockDim.x + threadIdx.x;
    if (e < NE) {
        int d = (int)ld_idx(ei, (long long)NE + e);
        atomicAdd(&g_degcnt[d], 1);
    }
}

__global__ void dinv_kernel() {
    int i = blockIdx.x * blockDim.x + threadIdx.x;
    if (i < NN) g_dinv[i] = rsqrtf(fmaxf((float)g_degcnt[i], 1.0f));
}

__global__ void scanA_kernel() {
    __shared__ int s[1024];
    int t = threadIdx.x;
    int idx = blockIdx.x * 1024 + t;
    int v = (idx < NN) ? g_degcnt[idx] : 0;
    s[t] = v;
    __syncthreads();
    for (int off = 1; off < 1024; off <<= 1) {
        int tmp = (t >= off) ? s[t - off] : 0;
        __syncthreads();
        if (t >= off) s[t] += tmp;
        __syncthreads();
    }
    if (idx < NN) g_offsets[idx] = s[t] - v;  // exclusive
    if (t == 1023) g_blocksums[blockIdx.x] = s[1023];
}

__global__ void scanB_kernel() {
    __shared__ int s[64];
    int t = threadIdx.x;
    int v = (t < SCAN_BLK) ? g_blocksums[t] : 0;
    s[t] = v;
    __syncthreads();
    for (int off = 1; off < 64; off <<= 1) {
        int tmp = (t >= off) ? s[t - off] : 0;
        __syncthreads();
        if (t >= off) s[t] += tmp;
        __syncthreads();
    }
    g_blockbase[t] = s[t] - v;  // exclusive
    if (t == 0) g_offsets[NN] = NE;
}

__global__ void scanC_kernel() {
    int idx = blockIdx.x * 1024 + threadIdx.x;
    if (idx < NN) g_offsets[idx] += g_blockbase[blockIdx.x];
}

__global__ void fill_kernel(const void* __restrict__ ei) {
    int e = blockIdx.x * blockDim.x + threadIdx.x;
    if (e < NE) {
        int s = (int)ld_idx(ei, e);
        int d = (int)ld_idx(ei, (long long)NE + e);
        int pos = g_offsets[d] + atomicAdd(&g_cursor[d], 1);
        g_srcs[pos]  = s;
        g_norms[pos] = g_dinv[s] * g_dinv[d];
    }
}

// ---------------- dense GEMM (M x K @ K x 64 + bias), optional relu on A ---
template <int K, bool RELU>
__device__ __forceinline__ void gemm_body(const float* __restrict__ A,
                                          const float* __restrict__ W,
                                          const float* __restrict__ bias,
                                          float* __restrict__ out) {
    __shared__ __align__(16) float Ws[K * 64];
    __shared__ __align__(16) float As[K * 32];  // [k][row], XOR-swizzled
    int t = threadIdx.x;
    int rowbase = blockIdx.x * 32;

    for (int i = t; i < K * 64; i += 256) Ws[i] = W[i];
    for (int i = t; i < 32 * K; i += 256) {
        int r = i / K, k = i - r * K;
        int row = rowbase + r;
        float v = 0.f;
        if (row < NN) {
            v = A[row * K + k];
            if (RELU) v = fmaxf(v, 0.f);
        }
        As[k * 32 + (r ^ (k & 31))] = v;
    }
    __syncthreads();

    int tx = t & 15, ty = t >> 4;  // cols 4*tx..4*tx+3 ; rows ty, ty+16
    float a00 = 0, a01 = 0, a02 = 0, a03 = 0;
    float a10 = 0, a11 = 0, a12 = 0, a13 = 0;
#pragma unroll 8
    for (int k = 0; k < K; k++) {
        float4 b4 = *(const float4*)&Ws[k * 64 + tx * 4];
        int sw = k & 31;
        float x0 = As[k * 32 + (ty ^ sw)];
        float x1 = As[k * 32 + ((ty + 16) ^ sw)];
        a00 = fmaf(x0, b4.x, a00); a01 = fmaf(x0, b4.y, a01);
        a02 = fmaf(x0, b4.z, a02); a03 = fmaf(x0, b4.w, a03);
        a10 = fmaf(x1, b4.x, a10); a11 = fmaf(x1, b4.y, a11);
        a12 = fmaf(x1, b4.z, a12); a13 = fmaf(x1, b4.w, a13);
    }
    int col = tx * 4;
    float4 bb = *(const float4*)&bias[col];
    int row0 = rowbase + ty;
    if (row0 < NN)
        *(float4*)&out[row0 * 64 + col] =
            make_float4(a00 + bb.x, a01 + bb.y, a02 + bb.z, a03 + bb.w);
    int row1 = row0 + 16;
    if (row1 < NN)
        *(float4*)&out[row1 * 64 + col] =
            make_float4(a10 + bb.x, a11 + bb.y, a12 + bb.z, a13 + bb.w);
}

__global__ void __launch_bounds__(256) gemm1_kernel(const float* __restrict__ x,
                                                    const float* __restrict__ W,
                                                    const float* __restrict__ b) {
    gemm_body<IND, false>(x, W, b, g_t1);
}
__global__ void __launch_bounds__(256) gemm2_kernel(const float* __restrict__ W,
                                                    const float* __restrict__ b) {
    gemm_body<HD, true>(g_agg1, W, b, g_t2);
}

// ---------------- CSR gather aggregation (no atomics) ----------------------
__device__ __forceinline__ void gather_body(const float* __restrict__ feat,
                                            float* __restrict__ out) {
    int gw = (blockIdx.x * blockDim.x + threadIdx.x) >> 5;  // node id
    int lane = threadIdx.x & 31;
    if (gw >= NN) return;
    int beg = g_offsets[gw], end = g_offsets[gw + 1];
    float ax = 0.f, ay = 0.f;
    const float2* f2 = (const float2*)feat;
    for (int e = beg; e < end; e++) {
        int s = g_srcs[e];     // uniform across warp -> broadcast
        float w = g_norms[e];
        float2 v = f2[s * 32 + lane];  // coalesced 256B row
        ax = fmaf(v.x, w, ax);
        ay = fmaf(v.y, w, ay);
    }
    ((float2*)out)[gw * 32 + lane] = make_float2(ax, ay);
}

__global__ void __launch_bounds__(256) gather1_kernel() { gather_body(g_t1, g_agg1); }
__global__ void __launch_bounds__(256) gather2_kernel() { gather_body(g_t2, g_agg2); }

// ---------------- segment-mean pooling over sorted batch -------------------
__global__ void pool_kernel(const void* __restrict__ batch, float* __restrict__ out) {
    __shared__ int sb[2];
    int g = blockIdx.x;
    if (threadIdx.x < 2) {
        long long key = (long long)g + threadIdx.x;
        int lo = 0, hi = NN;
        while (lo < hi) {
            int m = (lo + hi) >> 1;
            if (ld_idx(batch, m) < key) lo = m + 1; else hi = m;
        }
        sb[threadIdx.x] = lo;
    }
    __syncthreads();
    int beg = sb[0], end = sb[1];
    int c = threadIdx.x;  // 64 cols
    float sum = 0.f;
    for (int r = beg; r < end; r++) sum += fmaxf(g_agg2[r * 64 + c], 0.f);
    float cnt = (float)(end - beg);
    out[g * 64 + c] = sum / fmaxf(cnt, 1.0f);
}

// ---------------- driver ---------------------------------------------------
extern "C" void kernel_launch(void* const* d_in, const int* in_sizes, int n_in,
                              void* d_out, int out_size) {
    const float* x  = (const float*)d_in[0];
    const void*  ei = d_in[1];
    const void*  bt = d_in[2];
    const float* W1 = (const float*)d_in[3];
    const float* b1 = (const float*)d_in[4];
    const float* W2 = (const float*)d_in[5];
    const float* b2 = (const float*)d_in[6];
    float* out = (float*)d_out;

    detect_kernel<<<1, 32>>>(ei);
    zero_kernel<<<(NN + 255) / 256, 256>>>();
    count_kernel<<<(NE + 255) / 256, 256>>>(ei);
    dinv_kernel<<<(NN + 255) / 256, 256>>>();
    scanA_kernel<<<SCAN_BLK, 1024>>>();
    scanB_kernel<<<1, 64>>>();
    scanC_kernel<<<SCAN_BLK, 1024>>>();
    fill_kernel<<<(NE + 255) / 256, 256>>>(ei);

    gemm1_kernel<<<(NN + 31) / 32, 256>>>(x, W1, b1);
    gather1_kernel<<<(NN * 32 + 255) / 256, 256>>>();
    gemm2_kernel<<<(NN + 31) / 32, 256>>>(W2, b2);
    gather2_kernel<<<(NN * 32 + 255) / 256, 256>>>();
    pool_kernel<<<NG, 64>>>(bt, out);
}

// round 7
// speedup vs baseline: 1.2719x; 1.2719x over previous
#include <cuda_runtime.h>

#define NN 50000
#define NE 800000
#define IND 128
#define HD 64
#define OD 64
#define NG 512

static const int SCAN_BLK = (NN + 1023) / 1024;  // 49

// ---------------- scratch (__device__ globals: no allocs allowed) ----------
__device__ int   g_is64;
__device__ int   g_degcnt[NN];
__device__ int   g_cursor[NN];
__device__ int   g_offsets[NN + 1];
__device__ int   g_blocksums[64];
__device__ int   g_blockbase[64];
__device__ float g_dinv[NN];
__device__ int2  g_edge[NE];      // (src, norm-bits) packed: one 8B broadcast load
__device__ float g_t1[NN * HD];
__device__ float g_agg1[NN * HD];
__device__ float g_t2[NN * OD];
__device__ float g_agg2[NN * OD];

// ---------------- helpers --------------------------------------------------
typedef unsigned long long ull;

__device__ __forceinline__ long long ld_idx(const void* p, long long i) {
    if (g_is64) return ((const long long*)p)[i];
    return (long long)((const int*)p)[i];
}

__device__ __forceinline__ ull pack2(float x, float y) {
    ull r; asm("mov.b64 %0, {%1, %2};" : "=l"(r) : "f"(x), "f"(y)); return r;
}
__device__ __forceinline__ float2 unpack2(ull v) {
    float2 f; asm("mov.b64 {%0, %1}, %2;" : "=f"(f.x), "=f"(f.y) : "l"(v)); return f;
}
// d = a * b + d  (two independent fp32 FMAs, bit-identical to scalar fmaf)
__device__ __forceinline__ void ffma2(ull& d, ull a, ull b) {
    asm("fma.rn.f32x2 %0, %1, %2, %0;" : "+l"(d) : "l"(a), "l"(b));
}

// ---------------- init: zero counters + int64/int32 detect -----------------
__global__ void init_kernel(const void* __restrict__ ei) {
    int i = blockIdx.x * blockDim.x + threadIdx.x;
    if (i < NN) { g_degcnt[i] = 0; g_cursor[i] = 0; }
    if (i == 0) {
        const long long* p = (const long long*)ei;
        int ok = 1;
        for (int j = 0; j < 64; j++) {
            long long v = p[j];
            if (v < 0 || v >= NN) { ok = 0; break; }
        }
        g_is64 = ok;  // int32 data read as int64 fails the range check w.h.p.
    }
}

__global__ void count_kernel(const void* __restrict__ ei) {
    int e = blockIdx.x * blockDim.x + threadIdx.x;
    if (e < NE) {
        int d = (int)ld_idx(ei, (long long)NE + e);
        atomicAdd(&g_degcnt[d], 1);
    }
}

// scanA also produces dinv (reads degcnt anyway)
__global__ void scanA_kernel() {
    __shared__ int s[1024];
    int t = threadIdx.x;
    int idx = blockIdx.x * 1024 + t;
    int v = (idx < NN) ? g_degcnt[idx] : 0;
    s[t] = v;
    __syncthreads();
    for (int off = 1; off < 1024; off <<= 1) {
        int tmp = (t >= off) ? s[t - off] : 0;
        __syncthreads();
        if (t >= off) s[t] += tmp;
        __syncthreads();
    }
    if (idx < NN) {
        g_offsets[idx] = s[t] - v;  // exclusive
        g_dinv[idx] = rsqrtf(fmaxf((float)v, 1.0f));
    }
    if (t == 1023) g_blocksums[blockIdx.x] = s[1023];
}

__global__ void scanB_kernel() {
    __shared__ int s[64];
    int t = threadIdx.x;
    int v = (t < SCAN_BLK) ? g_blocksums[t] : 0;
    s[t] = v;
    __syncthreads();
    for (int off = 1; off < 64; off <<= 1) {
        int tmp = (t >= off) ? s[t - off] : 0;
        __syncthreads();
        if (t >= off) s[t] += tmp;
        __syncthreads();
    }
    g_blockbase[t] = s[t] - v;  // exclusive
    if (t == 0) g_offsets[NN] = NE;
}

__global__ void scanC_kernel() {
    int idx = blockIdx.x * 1024 + threadIdx.x;
    if (idx < NN) g_offsets[idx] += g_blockbase[blockIdx.x];
}

__global__ void fill_kernel(const void* __restrict__ ei) {
    int e = blockIdx.x * blockDim.x + threadIdx.x;
    if (e < NE) {
        int s = (int)ld_idx(ei, e);
        int d = (int)ld_idx(ei, (long long)NE + e);
        int pos = g_offsets[d] + atomicAdd(&g_cursor[d], 1);
        g_edge[pos] = make_int2(s, __float_as_int(g_dinv[s] * g_dinv[d]));
    }
}

// ---------------- dense GEMM: 64 rows x 64 cols per block, FFMA2 mainloop --
// Thread tile: 4 rows x 4 cols. As stored [k][row ^ (k & 28)] (4-aligned
// swizzle keeps the 4-row x-load a single LDS.128 while spreading banks).
template <int K, bool RELU>
__device__ __forceinline__ void gemm_body(const float* __restrict__ A,
                                          const float* __restrict__ W,
                                          const float* __restrict__ bias,
                                          float* __restrict__ out) {
    extern __shared__ float smem[];
    float* Ws = smem;           // K * 64
    float* As = smem + K * 64;  // K * 64
    const int t = threadIdx.x;
    const int rowbase = blockIdx.x * 64;
    constexpr int NQ = K / 4;

    {
        const float4* W4 = (const float4*)W;
        float4* Ws4 = (float4*)Ws;
        for (int i = t; i < K * 16; i += 256) Ws4[i] = W4[i];
    }
    for (int i = t; i < 64 * NQ; i += 256) {
        int r = i / NQ, kq = i - r * NQ;
        int row = rowbase + r;
        float4 v = make_float4(0.f, 0.f, 0.f, 0.f);
        if (row < NN) {
            v = ((const float4*)A)[row * NQ + kq];
            if (RELU) {
                v.x = fmaxf(v.x, 0.f); v.y = fmaxf(v.y, 0.f);
                v.z = fmaxf(v.z, 0.f); v.w = fmaxf(v.w, 0.f);
            }
        }
        int k0 = kq * 4;
        int rs = r ^ (k0 & 28);  // (k0+j)&28 == k0&28 for j<4
        As[(k0 + 0) * 64 + rs] = v.x;
        As[(k0 + 1) * 64 + rs] = v.y;
        As[(k0 + 2) * 64 + rs] = v.z;
        As[(k0 + 3) * 64 + rs] = v.w;
    }
    __syncthreads();

    const int tx = t & 15, ty = t >> 4;
    const int c0 = tx * 4;
    const int r0 = ty * 4;

    ull ac[4][2];
#pragma unroll
    for (int j = 0; j < 4; j++) { ac[j][0] = 0ULL; ac[j][1] = 0ULL; }

#pragma unroll 8
    for (int k = 0; k < K; k++) {
        const float* wrow = Ws + k * 64 + c0;
        ull b01 = *(const ull*)(wrow);
        ull b23 = *(const ull*)(wrow + 2);
        float4 xv = *(const float4*)(As + k * 64 + (r0 ^ (k & 28)));
        ull x0 = pack2(xv.x, xv.x);
        ull x1 = pack2(xv.y, xv.y);
        ull x2 = pack2(xv.z, xv.z);
        ull x3 = pack2(xv.w, xv.w);
        ffma2(ac[0][0], x0, b01); ffma2(ac[0][1], x0, b23);
        ffma2(ac[1][0], x1, b01); ffma2(ac[1][1], x1, b23);
        ffma2(ac[2][0], x2, b01); ffma2(ac[2][1], x2, b23);
        ffma2(ac[3][0], x3, b01); ffma2(ac[3][1], x3, b23);
    }

    float4 bb = *(const float4*)(bias + c0);
#pragma unroll
    for (int j = 0; j < 4; j++) {
        int row = rowbase + r0 + j;
        if (row < NN) {
            float2 p01 = unpack2(ac[j][0]);
            float2 p23 = unpack2(ac[j][1]);
            *(float4*)&out[row * 64 + c0] =
                make_float4(p01.x + bb.x, p01.y + bb.y, p23.x + bb.z, p23.y + bb.w);
        }
    }
}

__global__ void __launch_bounds__(256) gemm1_kernel(const float* __restrict__ x,
                                                    const float* __restrict__ W,
                                                    const float* __restrict__ b) {
    gemm_body<IND, false>(x, W, b, g_t1);
}
__global__ void __launch_bounds__(256) gemm2_kernel(const float* __restrict__ W,
                                                    const float* __restrict__ b) {
    gemm_body<HD, true>(g_agg1, W, b, g_t2);
}

// ---------------- CSR gather aggregation: 16 lanes (float4) per node -------
__device__ __forceinline__ void gather_body(const float* __restrict__ feat,
                                            float* __restrict__ out) {
    int tid = blockIdx.x * blockDim.x + threadIdx.x;
    int node = tid >> 4;
    int lane = tid & 15;
    if (node >= NN) return;
    int beg = g_offsets[node], end = g_offsets[node + 1];
    const float4* f4 = (const float4*)feat;
    float4 a0 = make_float4(0.f, 0.f, 0.f, 0.f);
    float4 a1 = make_float4(0.f, 0.f, 0.f, 0.f);
    int e = beg;
    for (; e + 2 <= end; e += 2) {
        int2 ed0 = g_edge[e];
        int2 ed1 = g_edge[e + 1];
        float4 v0 = f4[ed0.x * 16 + lane];
        float4 v1 = f4[ed1.x * 16 + lane];
        float w0 = __int_as_float(ed0.y);
        float w1 = __int_as_float(ed1.y);
        a0.x = fmaf(v0.x, w0, a0.x); a0.y = fmaf(v0.y, w0, a0.y);
        a0.z = fmaf(v0.z, w0, a0.z); a0.w = fmaf(v0.w, w0, a0.w);
        a1.x = fmaf(v1.x, w1, a1.x); a1.y = fmaf(v1.y, w1, a1.y);
        a1.z = fmaf(v1.z, w1, a1.z); a1.w = fmaf(v1.w, w1, a1.w);
    }
    if (e < end) {
        int2 ed = g_edge[e];
        float4 v = f4[ed.x * 16 + lane];
        float w = __int_as_float(ed.y);
        a0.x = fmaf(v.x, w, a0.x); a0.y = fmaf(v.y, w, a0.y);
        a0.z = fmaf(v.z, w, a0.z); a0.w = fmaf(v.w, w, a0.w);
    }
    ((float4*)out)[node * 16 + lane] =
        make_float4(a0.x + a1.x, a0.y + a1.y, a0.z + a1.z, a0.w + a1.w);
}

__global__ void __launch_bounds__(256) gather1_kernel() { gather_body(g_t1, g_agg1); }
__global__ void __launch_bounds__(256) gather2_kernel() { gather_body(g_t2, g_agg2); }

// ---------------- segment-mean pooling over sorted batch (relu fused) ------
__global__ void pool_kernel(const void* __restrict__ batch, float* __restrict__ out) {
    __shared__ int sb[2];
    int g = blockIdx.x;
    if (threadIdx.x < 2) {
        long long key = (long long)g + threadIdx.x;
        int lo = 0, hi = NN;
        while (lo < hi) {
            int m = (lo + hi) >> 1;
            if (ld_idx(batch, m) < key) lo = m + 1; else hi = m;
        }
        sb[threadIdx.x] = lo;
    }
    __syncthreads();
    int beg = sb[0], end = sb[1];
    int c = threadIdx.x;  // 64 cols
    float sum = 0.f;
    for (int r = beg; r < end; r++) sum += fmaxf(g_agg2[r * 64 + c], 0.f);
    float cnt = (float)(end - beg);
    out[g * 64 + c] = sum / fmaxf(cnt, 1.0f);
}

// ---------------- driver ---------------------------------------------------
extern "C" void kernel_launch(void* const* d_in, const int* in_sizes, int n_in,
                              void* d_out, int out_size) {
    const float* x  = (const float*)d_in[0];
    const void*  ei = d_in[1];
    const void*  bt = d_in[2];
    const float* W1 = (const float*)d_in[3];
    const float* b1 = (const float*)d_in[4];
    const float* W2 = (const float*)d_in[5];
    const float* b2 = (const float*)d_in[6];
    float* out = (float*)d_out;

    const int SMEM1 = 2 * IND * 64 * (int)sizeof(float);  // 65536
    const int SMEM2 = 2 * HD * 64 * (int)sizeof(float);   // 32768
    cudaFuncSetAttribute(gemm1_kernel, cudaFuncAttributeMaxDynamicSharedMemorySize, SMEM1);
    cudaFuncSetAttribute(gemm2_kernel, cudaFuncAttributeMaxDynamicSharedMemorySize, SMEM2);

    init_kernel<<<(NN + 255) / 256, 256>>>(ei);
    count_kernel<<<(NE + 255) / 256, 256>>>(ei);
    scanA_kernel<<<SCAN_BLK, 1024>>>();
    scanB_kernel<<<1, 64>>>();
    scanC_kernel<<<SCAN_BLK, 1024>>>();
    fill_kernel<<<(NE + 255) / 256, 256>>>(ei);

    gemm1_kernel<<<(NN + 63) / 64, 256, SMEM1>>>(x, W1, b1);
    gather1_kernel<<<(NN * 16 + 255) / 256, 256>>>();
    gemm2_kernel<<<(NN + 63) / 64, 256, SMEM2>>>(W2, b2);
    gather2_kernel<<<(NN * 16 + 255) / 256, 256>>>();
    pool_kernel<<<NG, 64>>>(bt, out);
}